// round 13
// baseline (speedup 1.0000x reference)
#include <cuda_runtime.h>
#include <cuda_fp16.h>
#include <stdint.h>

// Problem constants
#define BB  16
#define DD  256
#define HH  32
#define WW  32
#define NN  16384
#define KK  8192
#define CHW (DD*HH*WW)
#define HW  (HH*WW)

#define NCHUNK  128
#define GSZ     16
#define NGRP    (KK/GSZ)       // 512
#define MARGIN  2.5e-4f        // fp16 phase-1 error budget (>10x headroom)
#define PAIR_CAP (NN*64)
#define ESC     4096.0f        // e scale (exact pow2); |e*4096| <= 0.5
#define DSCALE  (-4.8828125e-4f)   // -2/4096 ; min(dv) == DSCALE*max(dotS)

// ---------------- device scratch (static globals; no allocation) -----------
__device__ __align__(16) float   g_zt[NN*DD];   // transposed z fp32 [n][d]
__device__ __align__(16) __half  g_zh[NN*DD];   // fp16 z [n][d]
__device__ __align__(16) __half  g_eh[KK*DD];   // fp16 e*4096 [k][d]
__device__ float          g_z2[NN];
__device__ float          g_e2[KK];
__device__ __align__(16) __half g_gmin[(size_t)NN*NGRP]; // [row][group] rd-fp16 min of (-2dot)
__device__ unsigned long long g_best[NN];
__device__ unsigned int   g_pairs[PAIR_CAP];
__device__ int            g_count;
__device__ float          g_partial[512];

// ---------------- helpers ---------------------------------------------------
__device__ __forceinline__ uint32_t smem_u32(const void* p) {
    uint32_t a;
    asm("{ .reg .u64 t; cvta.to.shared.u64 t, %1; cvt.u32.u64 %0, t; }" : "=r"(a) : "l"(p));
    return a;
}
__device__ __forceinline__ void ldsm4(uint32_t* r, uint32_t addr) {
    asm volatile("ldmatrix.sync.aligned.m8n8.x4.shared.b16 {%0,%1,%2,%3}, [%4];"
                 : "=r"(r[0]), "=r"(r[1]), "=r"(r[2]), "=r"(r[3]) : "r"(addr));
}
__device__ __forceinline__ void ldsm2(uint32_t* r, uint32_t addr) {
    asm volatile("ldmatrix.sync.aligned.m8n8.x2.shared.b16 {%0,%1}, [%2];"
                 : "=r"(r[0]), "=r"(r[1]) : "r"(addr));
}
// f16 inputs, f16 accumulators (2 b32 regs hold 4 halves)
__device__ __forceinline__ void mma_f16(uint32_t* c, const uint32_t* a, const uint32_t* b) {
    asm volatile("mma.sync.aligned.m16n8k16.row.col.f16.f16.f16.f16 "
                 "{%0,%1}, {%2,%3,%4,%5}, {%6,%7}, {%0,%1};"
                 : "+r"(c[0]), "+r"(c[1])
                 : "r"(a[0]), "r"(a[1]), "r"(a[2]), "r"(a[3]), "r"(b[0]), "r"(b[1]));
}

// ---------------- prep: transpose z + fp16 cast + z2 ------------------------
__global__ void __launch_bounds__(256) k_transpose(const float* __restrict__ z) {
    __shared__ float ts[256][33];
    int t = threadIdx.x, lane = t & 31, w = t >> 5;
    int n0 = blockIdx.x * 32;
    int b = n0 >> 10, s0 = n0 & 1023;
    const float* zp = z + (size_t)b * CHW + s0;
#pragma unroll 8
    for (int j = 0; j < 32; j++) {
        int d = j * 8 + w;
        ts[d][lane] = zp[(size_t)d * HW + lane];
    }
    __syncthreads();
#pragma unroll 8
    for (int j = 0; j < 32; j++) {
        float v = ts[t][j];
        size_t o = (size_t)(n0 + j) * DD + t;
        g_zt[o] = v;
        g_zh[o] = __float2half_rn(v);
    }
#pragma unroll
    for (int q = 0; q < 4; q++) {
        int nl = w * 4 + q;
        float s = 0.f;
#pragma unroll
        for (int jj = 0; jj < 8; jj++) { float v = ts[lane + 32 * jj][nl]; s = fmaf(v, v, s); }
#pragma unroll
        for (int m = 16; m; m >>= 1) s += __shfl_xor_sync(0xffffffffu, s, m);
        if (lane == 0) g_z2[n0 + nl] = s;
    }
}

// prep: fp16 cast of scaled embeddings + e2 ; also zero pair counter
__global__ void __launch_bounds__(256) k_prep_e(const float* __restrict__ emb) {
    if (blockIdx.x == 0 && threadIdx.x == 0) g_count = 0;
    int k = blockIdx.x * 8 + (threadIdx.x >> 5);
    int lane = threadIdx.x & 31;
    const float* p = emb + (size_t)k * DD;
    float sum = 0.f;
#pragma unroll
    for (int j = 0; j < DD / 32; j++) {
        float v = p[lane + 32 * j];
        sum = fmaf(v, v, sum);
        g_eh[(size_t)k * DD + lane + 32 * j] = __float2half_rn(v * ESC);
    }
#pragma unroll
    for (int m = 16; m; m >>= 1) sum += __shfl_xor_sync(0xffffffffu, sum, m);
    if (lane == 0) g_e2[k] = sum;
}

// ---------------- phase 1: fp16 HMMA (f16 acc) + per-group min --------------
// r4-proven skeleton: static smem, restage z+e per 64-d step, 2 syncs.
__global__ void __launch_bounds__(256, 2) k_mma() {
    __shared__ __align__(1024) __half zs[128 * 64];
    __shared__ __align__(1024) __half es[128 * 64];

    int t = threadIdx.x, lane = t & 31, wid = t >> 5;
    int wm = wid >> 2, wn = wid & 3;          // 2x4 warp grid, warp tile 64x32
    int n0 = blockIdx.x * 128;
    uint32_t zb = smem_u32(zs), eb = smem_u32(es);
    const __half* zg = g_zh + (size_t)n0 * DD;

    int sub  = lane >> 3;
    int arow = wm * 64 + ((sub & 1) << 3) + (lane & 7);  // + mi*16
    int acoff = sub >> 1;
    int brow = wn * 32 + (lane & 7);                     // + ni*8
    int bsub = (lane >> 3) & 1;

    for (int cc = 0; cc < 32; cc++) {
        int c = blockIdx.y * 32 + cc;
        const __half* eg = g_eh + (size_t)c * NCHUNK * DD;

        uint32_t acc[4][4][2];                // f16x2 accumulators
#pragma unroll
        for (int mi = 0; mi < 4; mi++)
#pragma unroll
            for (int ni = 0; ni < 4; ni++) { acc[mi][ni][0] = 0u; acc[mi][ni][1] = 0u; }

#pragma unroll 1
        for (int dc = 0; dc < 4; dc++) {
            __syncthreads();
            int d0 = dc * 64;
#pragma unroll
            for (int j = 0; j < 4; j++) {
                int f = t + j * 256;
                int r = f >> 3, ch = f & 7;
                uint32_t so = (uint32_t)(r * 128 + ((ch ^ (r & 7)) << 4));
                *(uint4*)((char*)zs + so) = *(const uint4*)(zg + (size_t)r * DD + d0 + ch * 8);
                *(uint4*)((char*)es + so) = *(const uint4*)(eg + (size_t)r * DD + d0 + ch * 8);
            }
            __syncthreads();
#pragma unroll
            for (int ks = 0; ks < 4; ks++) {
                uint32_t b[4][2];
#pragma unroll
                for (int ni = 0; ni < 4; ni++) {
                    int row = brow + ni * 8;
                    int ci  = ks * 2 + bsub;
                    ldsm2(b[ni], eb + (uint32_t)(row * 128 + ((ci ^ (row & 7)) << 4)));
                }
#pragma unroll
                for (int mi = 0; mi < 4; mi++) {
                    uint32_t a4[4];
                    int row = arow + mi * 16;
                    int ci  = ks * 2 + acoff;
                    ldsm4(a4, zb + (uint32_t)(row * 128 + ((ci ^ (row & 7)) << 4)));
#pragma unroll
                    for (int ni = 0; ni < 4; ni++)
                        mma_f16(acc[mi][ni], a4, b[ni]);
                }
            }
        }
        // epilogue: per-row per-16-col-group MAX of scaled dot; dv = DSCALE*max
#pragma unroll
        for (int mi = 0; mi < 4; mi++)
#pragma unroll
            for (int rh = 0; rh < 2; rh++) {
                __half2 m01 = __hmax2(*(__half2*)&acc[mi][0][rh], *(__half2*)&acc[mi][1][rh]);
                __half2 m23 = __hmax2(*(__half2*)&acc[mi][2][rh], *(__half2*)&acc[mi][3][rh]);
                float2 f0 = __half22float2(m01);
                float2 f1 = __half22float2(m23);
                float mx0 = fmaxf(f0.x, f0.y);
                float mx1 = fmaxf(f1.x, f1.y);
                mx0 = fmaxf(mx0, __shfl_xor_sync(0xffffffffu, mx0, 1));
                mx0 = fmaxf(mx0, __shfl_xor_sync(0xffffffffu, mx0, 2));
                mx1 = fmaxf(mx1, __shfl_xor_sync(0xffffffffu, mx1, 1));
                mx1 = fmaxf(mx1, __shfl_xor_sync(0xffffffffu, mx1, 2));
                if ((lane & 3) == 0) {
                    int row = n0 + wm * 64 + mi * 16 + rh * 8 + (lane >> 2);
                    size_t base = (size_t)row * NGRP + c * 8 + wn * 2;
                    __half2 hv;
                    hv.x = __float2half_rd(mx0 * DSCALE);
                    hv.y = __float2half_rd(mx1 * DSCALE);
                    *(__half2*)(g_gmin + base) = hv;
                }
            }
    }
}

// ---------------- phase 2a: scan gmin (fp16), emit candidate pairs ----------
__global__ void __launch_bounds__(256) k_gap() {
    int wid = threadIdx.x >> 5, lane = threadIdx.x & 31;
    int row = blockIdx.x * 8 + wid;
    const uint4* gm = (const uint4*)(g_gmin + (size_t)row * NGRP);
    uint4 va = gm[lane * 2], vb = gm[lane * 2 + 1];   // 16 halves = groups [lane*16, lane*16+16)
    float v[16];
    {
        uint32_t w[8] = {va.x, va.y, va.z, va.w, vb.x, vb.y, vb.z, vb.w};
#pragma unroll
        for (int i = 0; i < 8; i++) {
            float2 f = __half22float2(*(__half2*)&w[i]);
            v[i * 2] = f.x; v[i * 2 + 1] = f.y;
        }
    }
    float m = 3.4e38f;
#pragma unroll
    for (int i = 0; i < 16; i++) m = fminf(m, v[i]);
#pragma unroll
    for (int s = 16; s; s >>= 1) m = fminf(m, __shfl_xor_sync(0xffffffffu, m, s));
    float thr = m + MARGIN;
    if (lane == 0) g_best[row] = ~0ull;
#pragma unroll
    for (int i = 0; i < 16; i++) {
        if (v[i] <= thr) {
            int pos = atomicAdd(&g_count, 1);
            if (pos < PAIR_CAP) g_pairs[pos] = (unsigned)(row * NGRP + lane * 16 + i);
        }
    }
}

// ---------------- phase 2b: exact fp32 rescore of candidate groups ----------
__global__ void __launch_bounds__(256) k_rescore2(const float* __restrict__ emb) {
    __shared__ __align__(16) float zsh[8][256];
    int wid = threadIdx.x >> 5, lane = threadIdx.x & 31;
    int wi = blockIdx.x * 8 + wid;
    int stride = gridDim.x * 8;
    int cnt = g_count; if (cnt > PAIR_CAP) cnt = PAIR_CAP;

    for (int p = wi; p < cnt; p += stride) {
        unsigned e = g_pairs[p];
        int row = (int)(e >> 9), g = (int)(e & (NGRP - 1));
        float4* zs4 = (float4*)zsh[wid];
        const float4* zr4 = (const float4*)(g_zt + (size_t)row * DD);
        zs4[lane] = zr4[lane];
        zs4[lane + 32] = zr4[lane + 32];
        __syncwarp();
        float z2r = g_z2[row];
        int code = g * GSZ + (lane & 15);
        const float4* er = (const float4*)(emb + (size_t)code * DD);
        const float4* s4 = (const float4*)zsh[wid];
        float dot = 0.f;
#pragma unroll 16
        for (int d4 = 0; d4 < DD / 4; d4++) {
            float4 a = s4[d4], b2 = er[d4];
            dot = fmaf(a.x, b2.x, dot); dot = fmaf(a.y, b2.y, dot);
            dot = fmaf(a.z, b2.z, dot); dot = fmaf(a.w, b2.w, dot);
        }
        float dv = fmaf(-2.f, dot, z2r + g_e2[code]);
#pragma unroll
        for (int s = 16; s; s >>= 1) {
            float ov = __shfl_xor_sync(0xffffffffu, dv, s);
            int   oc = __shfl_xor_sync(0xffffffffu, code, s);
            if (ov < dv || (ov == dv && oc < code)) { dv = ov; code = oc; }
        }
        if (lane == 0) {
            unsigned long long key = ((unsigned long long)__float_as_uint(dv) << 13) | (unsigned)code;
            atomicMin(&g_best[row], key);
        }
        __syncwarp();
    }
}

// ---------------- epilogue: coalesced gather + loss -------------------------
__global__ void __launch_bounds__(256) k_quantize(
    const float* __restrict__ z, const float* __restrict__ emb, float* __restrict__ out) {
    __shared__ float esh[32][257];
    __shared__ int idxs[32];
    __shared__ float red[256];
    int t = threadIdx.x, lane = t & 31, w = t >> 5;
    int n0 = blockIdx.x * 32;
    if (t < 32) idxs[t] = (int)(g_best[n0 + t] & 0x1FFFull);
    __syncthreads();
#pragma unroll
    for (int q = 0; q < 4; q++) {
        int r = w * 4 + q;
        const float4* er = (const float4*)(emb + (size_t)idxs[r] * DD);
        float4 u = er[lane], v = er[lane + 32];
        int d0 = lane * 4;
        esh[r][d0 + 0] = u.x; esh[r][d0 + 1] = u.y; esh[r][d0 + 2] = u.z; esh[r][d0 + 3] = u.w;
        esh[r][128 + d0 + 0] = v.x; esh[r][128 + d0 + 1] = v.y;
        esh[r][128 + d0 + 2] = v.z; esh[r][128 + d0 + 3] = v.w;
    }
    __syncthreads();
    int b = n0 >> 10, s0 = n0 & 1023;
    const float* zp = z + (size_t)b * CHW + s0;
    float* op = out + (size_t)b * CHW + s0;
    float sq = 0.f;
    for (int d = w; d < DD; d += 8) {
        float e  = esh[lane][d];
        float zv = zp[(size_t)d * HW + lane];
        op[(size_t)d * HW + lane] = e;
        float diff = e - zv;
        sq = fmaf(diff, diff, sq);
    }
    red[t] = sq;
    __syncthreads();
#pragma unroll
    for (int st = 128; st; st >>= 1) {
        if (t < st) red[t] += red[t + st];
        __syncthreads();
    }
    if (t == 0) g_partial[blockIdx.x] = red[0];
}

__global__ void __launch_bounds__(256) k_finalize(float* __restrict__ out) {
    __shared__ float red[256];
    red[threadIdx.x] = g_partial[threadIdx.x] + g_partial[threadIdx.x + 256];
    __syncthreads();
#pragma unroll
    for (int st = 128; st; st >>= 1) {
        if (threadIdx.x < st) red[threadIdx.x] += red[threadIdx.x + st];
        __syncthreads();
    }
    if (threadIdx.x == 0) {
        float m = red[0] / 4194304.0f;
        out[(size_t)BB * CHW] = fmaf(0.25f, m, m);   // q_loss + 0.25*e_loss
    }
    for (int n = threadIdx.x; n < NN; n += 256)
        out[(size_t)BB * CHW + 1 + n] = (float)(int)(g_best[n] & 0x1FFFull);
}

// ---------------------------------------------------------------------------
extern "C" void kernel_launch(void* const* d_in, const int* in_sizes, int n_in,
                              void* d_out, int out_size) {
    const float* z   = (const float*)d_in[0];
    const float* emb = (const float*)d_in[1];
    float* out = (float*)d_out;

    k_transpose<<<NN / 32, 256>>>(z);
    k_prep_e<<<KK / 8, 256>>>(emb);
    k_mma<<<dim3(NN / 128, 2), 256>>>();
    k_gap<<<NN / 8, 256>>>();
    k_rescore2<<<NN / 8, 256>>>(emb);
    k_quantize<<<NN / 32, 256>>>(z, emb, out);
    k_finalize<<<1, 256>>>(out);
}

// round 16
// speedup vs baseline: 1.2412x; 1.2412x over previous
#include <cuda_runtime.h>
#include <cuda_bf16.h>
#include <cuda_fp16.h>
#include <stdint.h>

// Problem constants
#define BB  16
#define DD  256
#define HH  32
#define WW  32
#define NN  16384
#define KK  8192
#define CHW (DD*HH*WW)
#define HW  (HH*WW)

#define NCHUNK  128
#define GSZ     16
#define NGRP    (KK/GSZ)       // 512
#define MARGIN  2.5e-4f        // bf16 approx error budget

// ---------------- device scratch (static globals; no allocation) -----------
__device__ __align__(16) float          g_zt[NN*DD];   // transposed z fp32 [n][d]
__device__ __align__(16) __nv_bfloat16  g_zbf[NN*DD];  // bf16 [n][d]
__device__ __align__(16) __nv_bfloat16  g_ebf[KK*DD];  // bf16 [k][d]
__device__ float          g_z2[NN];
__device__ float          g_e2[KK];
__device__ __align__(16) __half g_gmin[(size_t)NN*NGRP]; // [row][group] rd-fp16 min of (e2-2dot)
__device__ int            g_idx[NN];
__device__ float          g_partial[512];

// ---------------- helpers ---------------------------------------------------
__device__ __forceinline__ uint32_t smem_u32(const void* p) {
    uint32_t a;
    asm("{ .reg .u64 t; cvta.to.shared.u64 t, %1; cvt.u32.u64 %0, t; }" : "=r"(a) : "l"(p));
    return a;
}
__device__ __forceinline__ void ldsm4(uint32_t* r, uint32_t addr) {
    asm volatile("ldmatrix.sync.aligned.m8n8.x4.shared.b16 {%0,%1,%2,%3}, [%4];"
                 : "=r"(r[0]), "=r"(r[1]), "=r"(r[2]), "=r"(r[3]) : "r"(addr));
}
__device__ __forceinline__ void ldsm2(uint32_t* r, uint32_t addr) {
    asm volatile("ldmatrix.sync.aligned.m8n8.x2.shared.b16 {%0,%1}, [%2];"
                 : "=r"(r[0]), "=r"(r[1]) : "r"(addr));
}
__device__ __forceinline__ void mma_bf16(float* c, const uint32_t* a, const uint32_t* b) {
    asm volatile("mma.sync.aligned.m16n8k16.row.col.f32.bf16.bf16.f32 "
                 "{%0,%1,%2,%3}, {%4,%5,%6,%7}, {%8,%9}, {%0,%1,%2,%3};"
                 : "+f"(c[0]), "+f"(c[1]), "+f"(c[2]), "+f"(c[3])
                 : "r"(a[0]), "r"(a[1]), "r"(a[2]), "r"(a[3]), "r"(b[0]), "r"(b[1]));
}

// ---------------- prep: transpose z + bf16 cast + z2 ------------------------
__global__ void __launch_bounds__(256) k_transpose(const float* __restrict__ z) {
    __shared__ float ts[256][33];
    int t = threadIdx.x, lane = t & 31, w = t >> 5;
    int n0 = blockIdx.x * 32;
    int b = n0 >> 10, s0 = n0 & 1023;
    const float* zp = z + (size_t)b * CHW + s0;
#pragma unroll 8
    for (int j = 0; j < 32; j++) {
        int d = j * 8 + w;
        ts[d][lane] = zp[(size_t)d * HW + lane];
    }
    __syncthreads();
#pragma unroll 8
    for (int j = 0; j < 32; j++) {
        float v = ts[t][j];
        size_t o = (size_t)(n0 + j) * DD + t;
        g_zt[o]  = v;
        g_zbf[o] = __float2bfloat16_rn(v);
    }
#pragma unroll
    for (int q = 0; q < 4; q++) {
        int nl = w * 4 + q;
        float s = 0.f;
#pragma unroll
        for (int jj = 0; jj < 8; jj++) { float v = ts[lane + 32 * jj][nl]; s = fmaf(v, v, s); }
#pragma unroll
        for (int m = 16; m; m >>= 1) s += __shfl_xor_sync(0xffffffffu, s, m);
        if (lane == 0) g_z2[n0 + nl] = s;
    }
}

// prep: bf16 cast of embeddings + e2
__global__ void __launch_bounds__(256) k_prep_e(const float* __restrict__ emb) {
    int k = blockIdx.x * 8 + (threadIdx.x >> 5);
    int lane = threadIdx.x & 31;
    const float* p = emb + (size_t)k * DD;
    float sum = 0.f;
#pragma unroll
    for (int j = 0; j < DD / 32; j++) {
        float v = p[lane + 32 * j];
        sum = fmaf(v, v, sum);
        g_ebf[(size_t)k * DD + lane + 32 * j] = __float2bfloat16_rn(v);
    }
#pragma unroll
    for (int m = 16; m; m >>= 1) sum += __shfl_xor_sync(0xffffffffu, sum, m);
    if (lane == 0) g_e2[k] = sum;
}

// no-op spacer so k_mma is the 4th launch (ncu profiles launch #4)
__global__ void k_init() {}

// ---------------- phase 1: bf16 HMMA GEMM + per-group min (r4 champion) ----
__global__ void __launch_bounds__(256, 2) k_mma() {
    __shared__ __align__(1024) __nv_bfloat16 zs[128 * 64];
    __shared__ __align__(1024) __nv_bfloat16 es[128 * 64];

    int t = threadIdx.x, lane = t & 31, wid = t >> 5;
    int wm = wid >> 2, wn = wid & 3;          // 2x4 warp grid, warp tile 64x32
    int n0 = blockIdx.x * 128;
    uint32_t zb = smem_u32(zs), eb = smem_u32(es);
    const __nv_bfloat16* zg = g_zbf + (size_t)n0 * DD;

    int sub  = lane >> 3;
    int arow = wm * 64 + ((sub & 1) << 3) + (lane & 7);  // + mi*16
    int acoff = sub >> 1;
    int brow = wn * 32 + (lane & 7);                     // + ni*8
    int bsub = (lane >> 3) & 1;

    for (int cc = 0; cc < 32; cc++) {
        int c = blockIdx.y * 32 + cc;
        const __nv_bfloat16* eg = g_ebf + (size_t)c * NCHUNK * DD;

        float acc[4][4][4];
#pragma unroll
        for (int mi = 0; mi < 4; mi++)
#pragma unroll
            for (int ni = 0; ni < 4; ni++)
#pragma unroll
                for (int q = 0; q < 4; q++) acc[mi][ni][q] = 0.f;

#pragma unroll 1
        for (int dc = 0; dc < 4; dc++) {
            __syncthreads();
            int d0 = dc * 64;
#pragma unroll
            for (int j = 0; j < 4; j++) {
                int f = t + j * 256;
                int r = f >> 3, ch = f & 7;
                uint32_t so = (uint32_t)(r * 128 + ((ch ^ (r & 7)) << 4));
                *(uint4*)((char*)zs + so) = *(const uint4*)(zg + (size_t)r * DD + d0 + ch * 8);
                *(uint4*)((char*)es + so) = *(const uint4*)(eg + (size_t)r * DD + d0 + ch * 8);
            }
            __syncthreads();
#pragma unroll
            for (int ks = 0; ks < 4; ks++) {
                uint32_t b[4][2];
#pragma unroll
                for (int ni = 0; ni < 4; ni++) {
                    int row = brow + ni * 8;
                    int ci  = ks * 2 + bsub;
                    ldsm2(b[ni], eb + (uint32_t)(row * 128 + ((ci ^ (row & 7)) << 4)));
                }
#pragma unroll
                for (int mi = 0; mi < 4; mi++) {
                    uint32_t a4[4];
                    int row = arow + mi * 16;
                    int ci  = ks * 2 + acoff;
                    ldsm4(a4, zb + (uint32_t)(row * 128 + ((ci ^ (row & 7)) << 4)));
#pragma unroll
                    for (int ni = 0; ni < 4; ni++)
                        mma_bf16(acc[mi][ni], a4, b[ni]);
                }
            }
        }
        // epilogue: per-row per-16-col-group min of (e2 - 2*dot), fp16 rd store
        float e2r[8];
#pragma unroll
        for (int ni = 0; ni < 4; ni++)
#pragma unroll
            for (int h = 0; h < 2; h++)
                e2r[ni * 2 + h] = __ldg(&g_e2[c * NCHUNK + wn * 32 + ni * 8 + (lane & 3) * 2 + h]);
#pragma unroll
        for (int mi = 0; mi < 4; mi++)
#pragma unroll
            for (int rh = 0; rh < 2; rh++) {
                float mp0 = 3.4e38f, mp1 = 3.4e38f;
#pragma unroll
                for (int ni = 0; ni < 4; ni++)
#pragma unroll
                    for (int h = 0; h < 2; h++) {
                        float dv = fmaf(-2.f, acc[mi][ni][rh * 2 + h], e2r[ni * 2 + h]);
                        if (ni < 2) { if (dv < mp0) mp0 = dv; }
                        else        { if (dv < mp1) mp1 = dv; }
                    }
                mp0 = fminf(mp0, __shfl_xor_sync(0xffffffffu, mp0, 1));
                mp0 = fminf(mp0, __shfl_xor_sync(0xffffffffu, mp0, 2));
                mp1 = fminf(mp1, __shfl_xor_sync(0xffffffffu, mp1, 1));
                mp1 = fminf(mp1, __shfl_xor_sync(0xffffffffu, mp1, 2));
                if ((lane & 3) == 0) {
                    int row = n0 + wm * 64 + mi * 16 + rh * 8 + (lane >> 2);
                    size_t base = (size_t)row * NGRP + c * 8 + wn * 2;
                    __half2 hv;
                    hv.x = __float2half_rd(mp0);
                    hv.y = __float2half_rd(mp1);
                    *(__half2*)(g_gmin + base) = hv;
                }
            }
    }
}

// ---------------- phase 2: exact fp32 rescore, monolithic (warp per row) ----
__global__ void __launch_bounds__(256) k_rescore(const float* __restrict__ emb) {
    __shared__ __align__(16) float zsh[8][256];
    __shared__ float gsh[8][512];
    int wid = threadIdx.x >> 5, lane = threadIdx.x & 31;
    int row = blockIdx.x * 8 + wid;

    const float4* zr4 = (const float4*)(g_zt + (size_t)row * DD);
    float4* zs4 = (float4*)zsh[wid];
    zs4[lane] = zr4[lane];
    zs4[lane + 32] = zr4[lane + 32];

    // load 512 fp16 gmins (256 u32), convert to fp32 smem, track min
    float m = 3.4e38f;
    const uint4* gm = (const uint4*)(g_gmin + (size_t)row * NGRP);
    uint4 va = gm[lane * 2], vb = gm[lane * 2 + 1];
    {
        uint32_t w[8] = {va.x, va.y, va.z, va.w, vb.x, vb.y, vb.z, vb.w};
#pragma unroll
        for (int i = 0; i < 8; i++) {
            float2 f = __half22float2(*(__half2*)&w[i]);
            gsh[wid][lane * 16 + i * 2]     = f.x;
            gsh[wid][lane * 16 + i * 2 + 1] = f.y;
            m = fminf(m, fminf(f.x, f.y));
        }
    }
#pragma unroll
    for (int s = 16; s; s >>= 1) m = fminf(m, __shfl_xor_sync(0xffffffffu, m, s));
    float thr = m + MARGIN;
    __syncwarp();

    float z2r = g_z2[row];
    float bestv = 3.4e38f;
    int besti = 0x7fffffff;
    const float4* s4 = (const float4*)zsh[wid];

    for (int g0 = 0; g0 < NGRP; g0 += 32) {
        unsigned mask = __ballot_sync(0xffffffffu, gsh[wid][g0 + lane] <= thr);
        while (mask) {
            int g = g0 + (__ffs(mask) - 1);
            mask &= mask - 1;
            float dv = 3.4e38f;
            int code = 0x7fffffff;
            if (lane < GSZ) {
                code = g * GSZ + lane;
                const float4* er = (const float4*)(emb + (size_t)code * DD);
                float dot = 0.f;
#pragma unroll 16
                for (int d4 = 0; d4 < DD / 4; d4++) {
                    float4 a = s4[d4], b = er[d4];
                    dot = fmaf(a.x, b.x, dot); dot = fmaf(a.y, b.y, dot);
                    dot = fmaf(a.z, b.z, dot); dot = fmaf(a.w, b.w, dot);
                }
                dv = fmaf(-2.f, dot, z2r + g_e2[code]);
            }
            if (dv < bestv || (dv == bestv && code < besti)) { bestv = dv; besti = code; }
        }
    }
#pragma unroll
    for (int s = 16; s; s >>= 1) {
        float ov = __shfl_xor_sync(0xffffffffu, bestv, s);
        int   oi = __shfl_xor_sync(0xffffffffu, besti, s);
        if (ov < bestv || (ov == bestv && oi < besti)) { bestv = ov; besti = oi; }
    }
    if (lane == 0) g_idx[row] = besti;
}

// ---------------- epilogue: coalesced gather + loss -------------------------
__global__ void __launch_bounds__(256) k_quantize(
    const float* __restrict__ z, const float* __restrict__ emb, float* __restrict__ out) {
    __shared__ float esh[32][257];
    __shared__ int idxs[32];
    __shared__ float red[256];
    int t = threadIdx.x, lane = t & 31, w = t >> 5;
    int n0 = blockIdx.x * 32;
    if (t < 32) idxs[t] = g_idx[n0 + t];
    __syncthreads();
#pragma unroll
    for (int q = 0; q < 4; q++) {
        int r = w * 4 + q;
        const float4* er = (const float4*)(emb + (size_t)idxs[r] * DD);
        float4 u = er[lane], v = er[lane + 32];
        int d0 = lane * 4;
        esh[r][d0 + 0] = u.x; esh[r][d0 + 1] = u.y; esh[r][d0 + 2] = u.z; esh[r][d0 + 3] = u.w;
        esh[r][128 + d0 + 0] = v.x; esh[r][128 + d0 + 1] = v.y;
        esh[r][128 + d0 + 2] = v.z; esh[r][128 + d0 + 3] = v.w;
    }
    __syncthreads();
    int b = n0 >> 10, s0 = n0 & 1023;
    const float* zp = z + (size_t)b * CHW + s0;
    float* op = out + (size_t)b * CHW + s0;
    float sq = 0.f;
    for (int d = w; d < DD; d += 8) {
        float e  = esh[lane][d];
        float zv = zp[(size_t)d * HW + lane];
        op[(size_t)d * HW + lane] = e;
        float diff = e - zv;
        sq = fmaf(diff, diff, sq);
    }
    red[t] = sq;
    __syncthreads();
#pragma unroll
    for (int st = 128; st; st >>= 1) {
        if (t < st) red[t] += red[t + st];
        __syncthreads();
    }
    if (t == 0) g_partial[blockIdx.x] = red[0];
}

__global__ void __launch_bounds__(256) k_finalize(float* __restrict__ out) {
    __shared__ float red[256];
    red[threadIdx.x] = g_partial[threadIdx.x] + g_partial[threadIdx.x + 256];
    __syncthreads();
#pragma unroll
    for (int st = 128; st; st >>= 1) {
        if (threadIdx.x < st) red[threadIdx.x] += red[threadIdx.x + st];
        __syncthreads();
    }
    if (threadIdx.x == 0) {
        float m = red[0] / 4194304.0f;
        out[(size_t)BB * CHW] = fmaf(0.25f, m, m);   // q_loss + 0.25*e_loss
    }
    for (int n = threadIdx.x; n < NN; n += 256)
        out[(size_t)BB * CHW + 1 + n] = (float)g_idx[n];
}

// ---------------------------------------------------------------------------
extern "C" void kernel_launch(void* const* d_in, const int* in_sizes, int n_in,
                              void* d_out, int out_size) {
    const float* z   = (const float*)d_in[0];
    const float* emb = (const float*)d_in[1];
    float* out = (float*)d_out;

    k_transpose<<<NN / 32, 256>>>(z);
    k_prep_e<<<KK / 8, 256>>>(emb);
    k_init<<<1, 32>>>();                       // spacer: k_mma becomes launch #4
    k_mma<<<dim3(NN / 128, 2), 256>>>();
    k_rescore<<<NN / 8, 256>>>(emb);
    k_quantize<<<NN / 32, 256>>>(z, emb, out);
    k_finalize<<<1, 256>>>(out);
}

// round 17
// speedup vs baseline: 1.4301x; 1.1522x over previous
#include <cuda_runtime.h>
#include <cuda_bf16.h>
#include <cuda_fp16.h>
#include <stdint.h>

// Problem constants
#define BB  16
#define DD  256
#define HH  32
#define WW  32
#define NN  16384
#define KK  8192
#define CHW (DD*HH*WW)
#define HW  (HH*WW)

#define NCHUNK  128
#define GSZ     16
#define NGRP    (KK/GSZ)       // 512
#define MARGIN  2.5e-4f        // bf16 approx error budget

#define SMEM_MMA (65536 + 32768)   // z persistent 64KB + e double-buffer 2x16KB

// ---------------- device scratch (static globals; no allocation) -----------
__device__ __align__(16) float          g_zt[NN*DD];   // transposed z fp32 [n][d]
__device__ __align__(16) __nv_bfloat16  g_zbf[NN*DD];  // bf16 [n][d]
__device__ __align__(16) __nv_bfloat16  g_ebf[KK*DD];  // bf16 [k][d]
__device__ float          g_z2[NN];
__device__ float          g_e2[KK];
__device__ __align__(16) __half g_gmin[(size_t)NN*NGRP]; // [row][group] rd-fp16 min of (e2-2dot)
__device__ int            g_idx[NN];
__device__ float          g_partial[512];

// ---------------- helpers ---------------------------------------------------
__device__ __forceinline__ uint32_t smem_u32(const void* p) {
    uint32_t a;
    asm("{ .reg .u64 t; cvta.to.shared.u64 t, %1; cvt.u32.u64 %0, t; }" : "=r"(a) : "l"(p));
    return a;
}
__device__ __forceinline__ void ldsm4(uint32_t* r, uint32_t addr) {
    asm volatile("ldmatrix.sync.aligned.m8n8.x4.shared.b16 {%0,%1,%2,%3}, [%4];"
                 : "=r"(r[0]), "=r"(r[1]), "=r"(r[2]), "=r"(r[3]) : "r"(addr));
}
__device__ __forceinline__ void mma_bf16(float* c, const uint32_t* a, const uint32_t* b) {
    asm volatile("mma.sync.aligned.m16n8k16.row.col.f32.bf16.bf16.f32 "
                 "{%0,%1,%2,%3}, {%4,%5,%6,%7}, {%8,%9}, {%0,%1,%2,%3};"
                 : "+f"(c[0]), "+f"(c[1]), "+f"(c[2]), "+f"(c[3])
                 : "r"(a[0]), "r"(a[1]), "r"(a[2]), "r"(a[3]), "r"(b[0]), "r"(b[1]));
}

// ---------------- prep: transpose z + bf16 cast + z2 ------------------------
__global__ void __launch_bounds__(256) k_transpose(const float* __restrict__ z) {
    __shared__ float ts[256][33];
    int t = threadIdx.x, lane = t & 31, w = t >> 5;
    int n0 = blockIdx.x * 32;
    int b = n0 >> 10, s0 = n0 & 1023;
    const float* zp = z + (size_t)b * CHW + s0;
#pragma unroll 8
    for (int j = 0; j < 32; j++) {
        int d = j * 8 + w;
        ts[d][lane] = zp[(size_t)d * HW + lane];
    }
    __syncthreads();
#pragma unroll 8
    for (int j = 0; j < 32; j++) {
        float v = ts[t][j];
        size_t o = (size_t)(n0 + j) * DD + t;
        g_zt[o]  = v;
        g_zbf[o] = __float2bfloat16_rn(v);
    }
#pragma unroll
    for (int q = 0; q < 4; q++) {
        int nl = w * 4 + q;
        float s = 0.f;
#pragma unroll
        for (int jj = 0; jj < 8; jj++) { float v = ts[lane + 32 * jj][nl]; s = fmaf(v, v, s); }
#pragma unroll
        for (int m = 16; m; m >>= 1) s += __shfl_xor_sync(0xffffffffu, s, m);
        if (lane == 0) g_z2[n0 + nl] = s;
    }
}

// prep: bf16 cast of embeddings + e2
__global__ void __launch_bounds__(256) k_prep_e(const float* __restrict__ emb) {
    int k = blockIdx.x * 8 + (threadIdx.x >> 5);
    int lane = threadIdx.x & 31;
    const float* p = emb + (size_t)k * DD;
    float sum = 0.f;
#pragma unroll
    for (int j = 0; j < DD / 32; j++) {
        float v = p[lane + 32 * j];
        sum = fmaf(v, v, sum);
        g_ebf[(size_t)k * DD + lane + 32 * j] = __float2bfloat16_rn(v);
    }
#pragma unroll
    for (int m = 16; m; m >>= 1) sum += __shfl_xor_sync(0xffffffffu, sum, m);
    if (lane == 0) g_e2[k] = sum;
}

// no-op spacer so k_mma is the 4th launch (ncu profiles launch #4)
__global__ void k_init() {}

// ---------------- phase 1: bf16 HMMA GEMM + per-group min -------------------
// smem: [0,64KB) persistent z (4 subtiles of 128x64), [64KB,96KB) e dbl buffer.
// One __syncthreads per 64-d step; e prefetched to regs under the MMA burst.
__global__ void __launch_bounds__(256, 2) k_mma() {
    extern __shared__ __align__(1024) char smem[];
    uint32_t sb = smem_u32(smem);
    uint32_t ebase = sb + 65536u;

    int t = threadIdx.x, lane = t & 31, wid = t >> 5;
    int wm = wid >> 2, wn = wid & 3;          // 2x4 warp grid, warp tile 64x32
    int n0 = blockIdx.x * 128;
    int c0 = blockIdx.y * 32;

    // staging pattern: f = t + j*256 -> row = rs + j*32, ch constant
    int rs = t >> 3, ch = t & 7;
    int csw = ch ^ (rs & 7);                  // swizzled 16B col (row&7 invariant mod 32)

    // persistent z tile: 128 rows x 256 bf16 = 64KB, subtile per 64-d slice
    {
        const __nv_bfloat16* zg = g_zbf + (size_t)n0 * DD;
#pragma unroll
        for (int j = 0; j < 16; j++) {
            int f = t + j * 256;
            int r = f >> 5, c32 = f & 31;
            int dcs = c32 >> 3, chz = c32 & 7;
            *(uint4*)(smem + dcs * 16384 + r * 128 + ((chz ^ (r & 7)) << 4)) =
                *(const uint4*)(zg + (size_t)r * DD + c32 * 8);
        }
    }
    // e stage 0
    {
        const __nv_bfloat16* ep = g_ebf + (size_t)c0 * NCHUNK * DD;
#pragma unroll
        for (int j = 0; j < 4; j++)
            *(uint4*)(smem + 65536 + (rs + j * 32) * 128 + (csw << 4)) =
                *(const uint4*)(ep + (size_t)(rs + j * 32) * DD + ch * 8);
    }
    __syncthreads();

    int sub  = lane >> 3;
    int arow = wm * 64 + ((sub & 1) << 3) + (lane & 7);  // + mi*16
    int acoff = sub >> 1;
    // B ldsm4: lane group g supplies matrix (ni = base + (g>>1), khalf = g&1)
    int bg = lane >> 3;
    int brow0 = wn * 32 + ((bg >> 1) << 3) + (lane & 7);
    int bh = bg & 1;

    for (int cc = 0; cc < 32; cc++) {
        float acc[4][4][4];
#pragma unroll
        for (int mi = 0; mi < 4; mi++)
#pragma unroll
            for (int ni = 0; ni < 4; ni++)
#pragma unroll
                for (int q = 0; q < 4; q++) acc[mi][ni][q] = 0.f;

#pragma unroll 1
        for (int dc = 0; dc < 4; dc++) {
            int s = cc * 4 + dc;
            // prefetch next 16KB e slice into regs (hidden under MMA burst)
            uint4 pf[4];
            bool has = (s + 1 < 128);
            if (has) {
                int ns = s + 1;
                const __nv_bfloat16* ep = g_ebf
                    + (size_t)(c0 + (ns >> 2)) * NCHUNK * DD + (ns & 3) * 64;
#pragma unroll
                for (int j = 0; j < 4; j++)
                    pf[j] = *(const uint4*)(ep + (size_t)(rs + j * 32) * DD + ch * 8);
            }
            uint32_t zsub = sb + (uint32_t)dc * 16384u;
            uint32_t ebuf = ebase + (uint32_t)(s & 1) * 16384u;
#pragma unroll
            for (int ks = 0; ks < 4; ks++) {
                uint32_t b01[4], b23[4];
                {
                    int ci = ks * 2 + bh;
                    ldsm4(b01, ebuf + (uint32_t)(brow0 * 128 + ((ci ^ (brow0 & 7)) << 4)));
                    int row2 = brow0 + 16;      // (row2 & 7) == (brow0 & 7)
                    ldsm4(b23, ebuf + (uint32_t)(row2 * 128 + ((ci ^ (brow0 & 7)) << 4)));
                }
#pragma unroll
                for (int mi = 0; mi < 4; mi++) {
                    uint32_t a4[4];
                    int row = arow + mi * 16;
                    int ci  = ks * 2 + acoff;
                    ldsm4(a4, zsub + (uint32_t)(row * 128 + ((ci ^ (row & 7)) << 4)));
                    mma_bf16(acc[mi][0], a4, b01 + 0);
                    mma_bf16(acc[mi][1], a4, b01 + 2);
                    mma_bf16(acc[mi][2], a4, b23 + 0);
                    mma_bf16(acc[mi][3], a4, b23 + 2);
                }
            }
            if (has) {
                int buf = (s + 1) & 1;
#pragma unroll
                for (int j = 0; j < 4; j++)
                    *(uint4*)(smem + 65536 + buf * 16384 + (rs + j * 32) * 128 + (csw << 4)) = pf[j];
            }
            __syncthreads();
        }
        // epilogue: per-row per-16-col-group min of (e2 - 2*dot), fp16 rd store
        int c = c0 + cc;
        float e2r[8];
#pragma unroll
        for (int ni = 0; ni < 4; ni++)
#pragma unroll
            for (int h = 0; h < 2; h++)
                e2r[ni * 2 + h] = __ldg(&g_e2[c * NCHUNK + wn * 32 + ni * 8 + (lane & 3) * 2 + h]);
#pragma unroll
        for (int mi = 0; mi < 4; mi++)
#pragma unroll
            for (int rh = 0; rh < 2; rh++) {
                float mp0 = 3.4e38f, mp1 = 3.4e38f;
#pragma unroll
                for (int ni = 0; ni < 4; ni++)
#pragma unroll
                    for (int h = 0; h < 2; h++) {
                        float dv = fmaf(-2.f, acc[mi][ni][rh * 2 + h], e2r[ni * 2 + h]);
                        if (ni < 2) { if (dv < mp0) mp0 = dv; }
                        else        { if (dv < mp1) mp1 = dv; }
                    }
                mp0 = fminf(mp0, __shfl_xor_sync(0xffffffffu, mp0, 1));
                mp0 = fminf(mp0, __shfl_xor_sync(0xffffffffu, mp0, 2));
                mp1 = fminf(mp1, __shfl_xor_sync(0xffffffffu, mp1, 1));
                mp1 = fminf(mp1, __shfl_xor_sync(0xffffffffu, mp1, 2));
                if ((lane & 3) == 0) {
                    int row = n0 + wm * 64 + mi * 16 + rh * 8 + (lane >> 2);
                    size_t base = (size_t)row * NGRP + c * 8 + wn * 2;
                    __half2 hv;
                    hv.x = __float2half_rd(mp0);
                    hv.y = __float2half_rd(mp1);
                    *(__half2*)(g_gmin + base) = hv;
                }
            }
    }
}

// ---------------- phase 2: exact fp32 rescore, monolithic (warp per row) ----
__global__ void __launch_bounds__(256) k_rescore(const float* __restrict__ emb) {
    __shared__ __align__(16) float zsh[8][256];
    __shared__ float gsh[8][512];
    int wid = threadIdx.x >> 5, lane = threadIdx.x & 31;
    int row = blockIdx.x * 8 + wid;

    const float4* zr4 = (const float4*)(g_zt + (size_t)row * DD);
    float4* zs4 = (float4*)zsh[wid];
    zs4[lane] = zr4[lane];
    zs4[lane + 32] = zr4[lane + 32];

    float m = 3.4e38f;
    const uint4* gm = (const uint4*)(g_gmin + (size_t)row * NGRP);
    uint4 va = gm[lane * 2], vb = gm[lane * 2 + 1];
    {
        uint32_t w[8] = {va.x, va.y, va.z, va.w, vb.x, vb.y, vb.z, vb.w};
#pragma unroll
        for (int i = 0; i < 8; i++) {
            float2 f = __half22float2(*(__half2*)&w[i]);
            gsh[wid][lane * 16 + i * 2]     = f.x;
            gsh[wid][lane * 16 + i * 2 + 1] = f.y;
            m = fminf(m, fminf(f.x, f.y));
        }
    }
#pragma unroll
    for (int s = 16; s; s >>= 1) m = fminf(m, __shfl_xor_sync(0xffffffffu, m, s));
    float thr = m + MARGIN;
    __syncwarp();

    float z2r = g_z2[row];
    float bestv = 3.4e38f;
    int besti = 0x7fffffff;
    const float4* s4 = (const float4*)zsh[wid];

    for (int g0 = 0; g0 < NGRP; g0 += 32) {
        unsigned mask = __ballot_sync(0xffffffffu, gsh[wid][g0 + lane] <= thr);
        while (mask) {
            int g = g0 + (__ffs(mask) - 1);
            mask &= mask - 1;
            float dv = 3.4e38f;
            int code = 0x7fffffff;
            if (lane < GSZ) {
                code = g * GSZ + lane;
                const float4* er = (const float4*)(emb + (size_t)code * DD);
                float dot = 0.f;
#pragma unroll 16
                for (int d4 = 0; d4 < DD / 4; d4++) {
                    float4 a = s4[d4], b = er[d4];
                    dot = fmaf(a.x, b.x, dot); dot = fmaf(a.y, b.y, dot);
                    dot = fmaf(a.z, b.z, dot); dot = fmaf(a.w, b.w, dot);
                }
                dv = fmaf(-2.f, dot, z2r + g_e2[code]);
            }
            if (dv < bestv || (dv == bestv && code < besti)) { bestv = dv; besti = code; }
        }
    }
#pragma unroll
    for (int s = 16; s; s >>= 1) {
        float ov = __shfl_xor_sync(0xffffffffu, bestv, s);
        int   oi = __shfl_xor_sync(0xffffffffu, besti, s);
        if (ov < bestv || (ov == bestv && oi < besti)) { bestv = ov; besti = oi; }
    }
    if (lane == 0) g_idx[row] = besti;
}

// ---------------- epilogue: coalesced gather + loss -------------------------
__global__ void __launch_bounds__(256) k_quantize(
    const float* __restrict__ z, const float* __restrict__ emb, float* __restrict__ out) {
    __shared__ float esh[32][257];
    __shared__ int idxs[32];
    __shared__ float red[256];
    int t = threadIdx.x, lane = t & 31, w = t >> 5;
    int n0 = blockIdx.x * 32;
    if (t < 32) idxs[t] = g_idx[n0 + t];
    __syncthreads();
#pragma unroll
    for (int q = 0; q < 4; q++) {
        int r = w * 4 + q;
        const float4* er = (const float4*)(emb + (size_t)idxs[r] * DD);
        float4 u = er[lane], v = er[lane + 32];
        int d0 = lane * 4;
        esh[r][d0 + 0] = u.x; esh[r][d0 + 1] = u.y; esh[r][d0 + 2] = u.z; esh[r][d0 + 3] = u.w;
        esh[r][128 + d0 + 0] = v.x; esh[r][128 + d0 + 1] = v.y;
        esh[r][128 + d0 + 2] = v.z; esh[r][128 + d0 + 3] = v.w;
    }
    __syncthreads();
    int b = n0 >> 10, s0 = n0 & 1023;
    const float* zp = z + (size_t)b * CHW + s0;
    float* op = out + (size_t)b * CHW + s0;
    float sq = 0.f;
    for (int d = w; d < DD; d += 8) {
        float e  = esh[lane][d];
        float zv = zp[(size_t)d * HW + lane];
        op[(size_t)d * HW + lane] = e;
        float diff = e - zv;
        sq = fmaf(diff, diff, sq);
    }
    red[t] = sq;
    __syncthreads();
#pragma unroll
    for (int st = 128; st; st >>= 1) {
        if (t < st) red[t] += red[t + st];
        __syncthreads();
    }
    if (t == 0) g_partial[blockIdx.x] = red[0];
}

__global__ void __launch_bounds__(256) k_finalize(float* __restrict__ out) {
    __shared__ float red[256];
    red[threadIdx.x] = g_partial[threadIdx.x] + g_partial[threadIdx.x + 256];
    __syncthreads();
#pragma unroll
    for (int st = 128; st; st >>= 1) {
        if (threadIdx.x < st) red[threadIdx.x] += red[threadIdx.x + st];
        __syncthreads();
    }
    if (threadIdx.x == 0) {
        float m = red[0] / 4194304.0f;
        out[(size_t)BB * CHW] = fmaf(0.25f, m, m);   // q_loss + 0.25*e_loss
    }
    for (int n = threadIdx.x; n < NN; n += 256)
        out[(size_t)BB * CHW + 1 + n] = (float)g_idx[n];
}

// ---------------------------------------------------------------------------
extern "C" void kernel_launch(void* const* d_in, const int* in_sizes, int n_in,
                              void* d_out, int out_size) {
    const float* z   = (const float*)d_in[0];
    const float* emb = (const float*)d_in[1];
    float* out = (float*)d_out;

    cudaFuncSetAttribute(k_mma, cudaFuncAttributeMaxDynamicSharedMemorySize, SMEM_MMA);

    k_transpose<<<NN / 32, 256>>>(z);
    k_prep_e<<<KK / 8, 256>>>(emb);
    k_init<<<1, 32>>>();                       // spacer: k_mma stays launch #4
    k_mma<<<dim3(NN / 128, 2), 256, SMEM_MMA>>>();
    k_rescore<<<NN / 8, 256>>>(emb);
    k_quantize<<<NN / 32, 256>>>(z, emb, out);
    k_finalize<<<1, 256>>>(out);
}